// round 12
// baseline (speedup 1.0000x reference)
#include <cuda_runtime.h>
#include <cstdint>

// Batched GEMM, mma.sync fp16 m16n8k16 + ldmatrix, warp-specialized.
// Round-12: 4 consumer warps (pure ldmatrix+MMA, R9-proven 64x64 warp tiles)
// + 1 producer warp (all LDG -> cvt.rn.f16x2 -> STS staging) over a 3-stage
// fp16 ring with full/empty mbarriers. No __syncthreads in the main loop;
// consumers carry zero staging instructions and fit regs without spills.
//
//   x:    [B=16, M=256, K=512]  (K contiguous)
//   path: [B=16, K=512, N=2048] (N contiguous)
//   out:  [B=16, M=256, N=2048]
//
// CTA 128x128, BK=32, 160 threads, 2 CTAs/SM.

constexpr int Mm = 256, Kk = 512, Nn = 2048;
constexpr int BM = 128, BN = 128, BK = 32;
constexpr int THREADS = 160;   // warps 0-3 consumers, warp 4 producer
constexpr int KT = Kk / BK;    // 16
constexpr int NSTAGE = 3;

constexpr int A_STRIDE_H = 40;   // fp16 units (80B rows) - R9-proven
constexpr int B_STRIDE_H = 136;  // fp16 units (272B rows)
constexpr int AH_B = BM * A_STRIDE_H * 2;   // 10240 B
constexpr int BH_B = BK * B_STRIDE_H * 2;   // 8704 B
constexpr int SH_B = AH_B + BH_B;           // 18944 B
constexpr int DATA_OFF = 64;                // mbarriers in [0,48)
constexpr int SMEM_BYTES = DATA_OFF + NSTAGE * SH_B;  // 56896

__device__ __forceinline__ uint32_t smem_u32(const void* ptr) {
    uint32_t a;
    asm("{ .reg .u64 t; cvta.to.shared.u64 t, %1; cvt.u32.u64 %0, t; }"
        : "=r"(a) : "l"(ptr));
    return a;
}
__device__ __forceinline__ uint32_t h2pack(float lo, float hi) {
    uint32_t r;
    asm("cvt.rn.f16x2.f32 %0, %1, %2;" : "=r"(r) : "f"(hi), "f"(lo));
    return r;
}
__device__ __forceinline__ void mbar_init(uint32_t a, uint32_t n) {
    asm volatile("mbarrier.init.shared.b64 [%0], %1;" :: "r"(a), "r"(n) : "memory");
}
__device__ __forceinline__ void mbar_arrive(uint32_t a) {
    asm volatile("mbarrier.arrive.shared.b64 _, [%0];" :: "r"(a) : "memory");
}
__device__ __forceinline__ void mbar_wait(uint32_t a, uint32_t parity) {
    asm volatile(
        "{\n\t.reg .pred P;\n\t"
        "W_%=:\n\t"
        "mbarrier.try_wait.parity.acquire.cta.shared::cta.b64 P, [%0], %1, 0x989680;\n\t"
        "@!P bra W_%=;\n\t}"
        :: "r"(a), "r"(parity) : "memory");
}
__device__ __forceinline__ void ldmatrix_x4(uint32_t& r0, uint32_t& r1,
                                            uint32_t& r2, uint32_t& r3, uint32_t addr) {
    asm volatile("ldmatrix.sync.aligned.m8n8.x4.shared.b16 {%0,%1,%2,%3}, [%4];"
                 : "=r"(r0), "=r"(r1), "=r"(r2), "=r"(r3) : "r"(addr));
}
__device__ __forceinline__ void ldmatrix_x4_trans(uint32_t& r0, uint32_t& r1,
                                                  uint32_t& r2, uint32_t& r3, uint32_t addr) {
    asm volatile("ldmatrix.sync.aligned.m8n8.x4.trans.shared.b16 {%0,%1,%2,%3}, [%4];"
                 : "=r"(r0), "=r"(r1), "=r"(r2), "=r"(r3) : "r"(addr));
}
__device__ __forceinline__ void mma_f16(float& c0, float& c1, float& c2, float& c3,
                                        uint32_t a0, uint32_t a1, uint32_t a2, uint32_t a3,
                                        uint32_t b0, uint32_t b1) {
    asm volatile(
        "mma.sync.aligned.m16n8k16.row.col.f32.f16.f16.f32 "
        "{%0,%1,%2,%3}, {%4,%5,%6,%7}, {%8,%9}, {%0,%1,%2,%3};"
        : "+f"(c0), "+f"(c1), "+f"(c2), "+f"(c3)
        : "r"(a0), "r"(a1), "r"(a2), "r"(a3), "r"(b0), "r"(b1));
}

__global__ __launch_bounds__(THREADS, 2)
void bmm_mma_f16_ws(const float* __restrict__ A,
                    const float* __restrict__ B,
                    float* __restrict__ C) {
    extern __shared__ char smem[];
    const uint32_t sb = smem_u32(smem);

    const int tid = threadIdx.x;
    const int wid = tid >> 5;
    const int lane = tid & 31;
    const int b  = blockIdx.z;
    const int by = blockIdx.y;
    const int n0 = blockIdx.x * BN;

    const float* Ab = A + (size_t)b * Mm * Kk + (size_t)by * BM * Kk;
    const float* Bb = B + (size_t)b * Kk * Nn + n0;
    float*       Cb = C + (size_t)b * Mm * Nn + (size_t)by * BM * Nn + n0;

    // mbarriers: full[s] @ 8s, empty[s] @ 24+8s
    if (tid == 0) {
#pragma unroll
        for (int s = 0; s < NSTAGE; s++) {
            mbar_init(sb + 8 * s, 32);        // full: 32 producer lanes
            mbar_init(sb + 24 + 8 * s, 128);  // empty: 128 consumer threads
        }
    }
    __syncthreads();

    if (wid == 4) {
        // ================= producer warp =================
        // Per kt: 2048 float4 chunks (A: 0..1023, B: 1024..2047).
        // Lane handles chunk c = 32*i + lane, i in 0..63, in 4 groups of 16,
        // double-buffered in registers.
        float4 rbuf[2][16];

        auto ldg_group = [&](int kt, int g, float4* r) {
            const float* Asrc = Ab + (size_t)kt * BK;
            const float* Bsrc = Bb + (size_t)kt * BK * Nn;
#pragma unroll
            for (int j = 0; j < 16; j++) {
                int i = g * 16 + j;
                int c = 32 * i + lane;
                if (i < 32) {
                    r[j] = *(const float4*)(Asrc + (size_t)(c >> 3) * Kk + (c & 7) * 4);
                } else {
                    int c2 = c - 1024;
                    r[j] = *(const float4*)(Bsrc + (size_t)(c2 >> 5) * Nn + (c2 & 31) * 4);
                }
            }
        };
        auto sts_group = [&](int s, int g, const float4* r) {
            char* bh = smem + DATA_OFF + s * SH_B;
#pragma unroll
            for (int j = 0; j < 16; j++) {
                int i = g * 16 + j;
                int c = 32 * i + lane;
                uint2 p = make_uint2(h2pack(r[j].x, r[j].y), h2pack(r[j].z, r[j].w));
                if (i < 32) {
                    *(uint2*)(bh + (c >> 3) * (A_STRIDE_H * 2) + (c & 7) * 8) = p;
                } else {
                    int c2 = c - 1024;
                    *(uint2*)(bh + AH_B + (c2 >> 5) * (B_STRIDE_H * 2) + (c2 & 31) * 8) = p;
                }
            }
        };

        ldg_group(0, 0, rbuf[0]);
        int ep0 = 1, ep1 = 1, ep2 = 1;  // producer empty-parities start at 1

#pragma unroll 1
        for (int kt = 0; kt < KT; kt++) {
            const int s = kt % NSTAGE;
            int ep = (s == 0) ? ep0 : (s == 1) ? ep1 : ep2;
            mbar_wait(sb + 24 + 8 * s, ep);
            if (s == 0) ep0 ^= 1; else if (s == 1) ep1 ^= 1; else ep2 ^= 1;

#pragma unroll
            for (int g = 0; g < 4; g++) {
                const int cur = g & 1;
                if (g < 3)            ldg_group(kt, g + 1, rbuf[cur ^ 1]);
                else if (kt + 1 < KT) ldg_group(kt + 1, 0, rbuf[cur ^ 1]);
                sts_group(s, g, rbuf[cur]);
            }
            mbar_arrive(sb + 8 * s);   // full[s]
        }
    } else {
        // ================= consumer warps (0-3) =================
        const int warp_m = wid >> 1;
        const int warp_n = wid & 1;
        const int m_base = warp_m * 64;
        const int nb     = warp_n * 64;
        const int g = lane >> 2;
        const int t = lane & 3;
        const int lrow8 = (lane & 7) + ((lane >> 3) & 1) * 8;
        const int lk8   = ((lane >> 4) & 1) * 8;

        float acc[4][8][4];
#pragma unroll
        for (int i = 0; i < 4; i++)
#pragma unroll
            for (int j = 0; j < 8; j++)
#pragma unroll
                for (int r = 0; r < 4; r++) acc[i][j][r] = 0.0f;

        int fp0 = 0, fp1 = 0, fp2 = 0;  // consumer full-parities start at 0

#pragma unroll 1
        for (int kt = 0; kt < KT; kt++) {
            const int s = kt % NSTAGE;
            int fp = (s == 0) ? fp0 : (s == 1) ? fp1 : fp2;
            mbar_wait(sb + 8 * s, fp);
            if (s == 0) fp0 ^= 1; else if (s == 1) fp1 ^= 1; else fp2 ^= 1;

            const uint32_t AHb = sb + DATA_OFF + s * SH_B;
            const uint32_t BHb = AHb + AH_B;

#pragma unroll
            for (int ks = 0; ks < 2; ks++) {
                const int k0 = ks * 16;

                uint32_t af[4][4];
#pragma unroll
                for (int i = 0; i < 4; i++) {
                    uint32_t addr = AHb
                        + (m_base + i * 16 + lrow8) * (A_STRIDE_H * 2)
                        + (k0 + lk8) * 2;
                    ldmatrix_x4(af[i][0], af[i][1], af[i][2], af[i][3], addr);
                }
                uint32_t bf[4][4];
#pragma unroll
                for (int j2 = 0; j2 < 4; j2++) {
                    uint32_t addr = BHb
                        + (k0 + lrow8) * (B_STRIDE_H * 2)
                        + (nb + j2 * 16 + lk8) * 2;
                    ldmatrix_x4_trans(bf[j2][0], bf[j2][1], bf[j2][2], bf[j2][3], addr);
                }
#pragma unroll
                for (int i = 0; i < 4; i++)
#pragma unroll
                    for (int j = 0; j < 8; j++) {
                        const int j2 = j >> 1, h = (j & 1) * 2;
                        mma_f16(acc[i][j][0], acc[i][j][1], acc[i][j][2], acc[i][j][3],
                                af[i][0], af[i][1], af[i][2], af[i][3],
                                bf[j2][h + 0], bf[j2][h + 1]);
                    }
            }
            mbar_arrive(sb + 24 + 8 * s);  // empty[s]
        }

        // ---- epilogue (standard m16n8 C layout) ----
#pragma unroll
        for (int i = 0; i < 4; i++) {
            const int row0 = m_base + i * 16 + g;
#pragma unroll
            for (int j = 0; j < 8; j++) {
                const int col = nb + j * 8 + 2 * t;
                *(float2*)(Cb + (size_t)row0 * Nn + col) =
                    make_float2(acc[i][j][0], acc[i][j][1]);
                *(float2*)(Cb + (size_t)(row0 + 8) * Nn + col) =
                    make_float2(acc[i][j][2], acc[i][j][3]);
            }
        }
    }
}

extern "C" void kernel_launch(void* const* d_in, const int* in_sizes, int n_in,
                              void* d_out, int out_size) {
    const float* x    = (const float*)d_in[0];  // [16, 256, 512]
    const float* path = (const float*)d_in[1];  // [16, 512, 2048]
    float* out = (float*)d_out;                 // [16, 256, 2048]

    cudaFuncSetAttribute(bmm_mma_f16_ws,
                         cudaFuncAttributeMaxDynamicSharedMemorySize, SMEM_BYTES);

    dim3 grid(Nn / BN, Mm / BM, 16);  // (16, 2, 16) = 512 CTAs
    bmm_mma_f16_ws<<<grid, THREADS, SMEM_BYTES>>>(x, path, out);
}

// round 13
// speedup vs baseline: 1.5127x; 1.5127x over previous
#include <cuda_runtime.h>
#include <cstdint>

// Batched GEMM, mma.sync fp16 m16n8k16 + ldmatrix (round-9 core).
// Round-13: split prefetch. A(kt+1) is LDG'd at the top of the k-step and
// STS'd between the two k16 MMA blocks; the SAME 8 float4 registers are then
// reused to LDG B(kt+1), STS'd after the second MMA block. Prefetch regs
// 64 -> 32 (total ~220, no spills) and the staging stores hide under MMA.
//
//   x:    [B=16, M=256, K=512]  (K contiguous)
//   path: [B=16, K=512, N=2048] (N contiguous)
//   out:  [B=16, M=256, N=2048]
//
// CTA 128x128, BK=32, 128 threads (4 warps, 64x64 warp tiles), 2 CTAs/SM.

constexpr int Mm = 256, Kk = 512, Nn = 2048;
constexpr int BM = 128, BN = 128, BK = 32;
constexpr int THREADS = 128;
constexpr int KT = Kk / BK;  // 16

constexpr int A_STRIDE_H = 40;   // fp16 units (80B rows) - R9-proven
constexpr int B_STRIDE_H = 136;  // fp16 units (272B rows)
constexpr int AH_B = BM * A_STRIDE_H * 2;   // 10240 B
constexpr int BH_B = BK * B_STRIDE_H * 2;   // 8704 B
constexpr int SH_B = AH_B + BH_B;           // 18944 B

__device__ __forceinline__ uint32_t smem_u32(const void* ptr) {
    uint32_t a;
    asm("{ .reg .u64 t; cvta.to.shared.u64 t, %1; cvt.u32.u64 %0, t; }"
        : "=r"(a) : "l"(ptr));
    return a;
}
__device__ __forceinline__ uint32_t h2pack(float lo, float hi) {
    uint32_t r;
    asm("cvt.rn.f16x2.f32 %0, %1, %2;" : "=r"(r) : "f"(hi), "f"(lo));
    return r;
}
__device__ __forceinline__ void ldmatrix_x4(uint32_t& r0, uint32_t& r1,
                                            uint32_t& r2, uint32_t& r3, uint32_t addr) {
    asm volatile("ldmatrix.sync.aligned.m8n8.x4.shared.b16 {%0,%1,%2,%3}, [%4];"
                 : "=r"(r0), "=r"(r1), "=r"(r2), "=r"(r3) : "r"(addr));
}
__device__ __forceinline__ void ldmatrix_x4_trans(uint32_t& r0, uint32_t& r1,
                                                  uint32_t& r2, uint32_t& r3, uint32_t addr) {
    asm volatile("ldmatrix.sync.aligned.m8n8.x4.trans.shared.b16 {%0,%1,%2,%3}, [%4];"
                 : "=r"(r0), "=r"(r1), "=r"(r2), "=r"(r3) : "r"(addr));
}
__device__ __forceinline__ void mma_f16(float& c0, float& c1, float& c2, float& c3,
                                        uint32_t a0, uint32_t a1, uint32_t a2, uint32_t a3,
                                        uint32_t b0, uint32_t b1) {
    asm volatile(
        "mma.sync.aligned.m16n8k16.row.col.f32.f16.f16.f32 "
        "{%0,%1,%2,%3}, {%4,%5,%6,%7}, {%8,%9}, {%0,%1,%2,%3};"
        : "+f"(c0), "+f"(c1), "+f"(c2), "+f"(c3)
        : "r"(a0), "r"(a1), "r"(a2), "r"(a3), "r"(b0), "r"(b1));
}

__global__ __launch_bounds__(THREADS, 2)
void bmm_mma_f16_sp(const float* __restrict__ A,
                    const float* __restrict__ B,
                    float* __restrict__ C) {
    __shared__ __align__(16) char smem_raw[2 * SH_B];
    const uint32_t sb = smem_u32(smem_raw);

    const int tid = threadIdx.x;
    const int wid = tid >> 5;
    const int lane = tid & 31;
    const int b  = blockIdx.z;
    const int by = blockIdx.y;
    const int n0 = blockIdx.x * BN;

    const float* Ab = A + (size_t)b * Mm * Kk + (size_t)by * BM * Kk;
    const float* Bb = B + (size_t)b * Kk * Nn + n0;
    float*       Cb = C + (size_t)b * Mm * Nn + (size_t)by * BM * Nn + n0;

    // ---- staging mappings: 8 float4 chunks each of A and B per thread ----
    // A tile: 128 rows x 32 floats -> chunk i: row = i>>3, kq = (i&7)*4
    // B tile: 32 rows x 128 floats -> chunk i: krow = i>>5, n = (i&31)*4
    const float* aSrc[8];
    const float* bSrc[8];
    uint32_t aOff[8], bOff[8];
#pragma unroll
    for (int j = 0; j < 8; j++) {
        int i = j * 128 + tid;
        int row = i >> 3, kq = (i & 7) * 4;
        aSrc[j] = Ab + (size_t)row * Kk + kq;
        aOff[j] = row * (A_STRIDE_H * 2) + kq * 2;
        int krow = i >> 5, n = (i & 31) * 4;
        bSrc[j] = Bb + (size_t)krow * Nn + n;
        bOff[j] = AH_B + krow * (B_STRIDE_H * 2) + n * 2;
    }

    float4 pR[8];  // shared prefetch buffer (A, then reused for B)

    auto ldg_A = [&](int kt) {
#pragma unroll
        for (int j = 0; j < 8; j++) pR[j] = *(const float4*)(aSrc[j] + (size_t)kt * BK);
    };
    auto ldg_B = [&](int kt) {
#pragma unroll
        for (int j = 0; j < 8; j++) pR[j] = *(const float4*)(bSrc[j] + (size_t)kt * BK * Nn);
    };
    auto sts_A = [&](int s) {
        const uint32_t soff = s * SH_B;
#pragma unroll
        for (int j = 0; j < 8; j++) {
            uint2 p = make_uint2(h2pack(pR[j].x, pR[j].y), h2pack(pR[j].z, pR[j].w));
            *(uint2*)(smem_raw + aOff[j] + soff) = p;
        }
    };
    auto sts_B = [&](int s) {
        const uint32_t soff = s * SH_B;
#pragma unroll
        for (int j = 0; j < 8; j++) {
            uint2 p = make_uint2(h2pack(pR[j].x, pR[j].y), h2pack(pR[j].z, pR[j].w));
            *(uint2*)(smem_raw + bOff[j] + soff) = p;
        }
    };

    // ---- compute mapping: 4 warps, 2x2 of 64x64 warp tiles ----
    const int warp_m = wid >> 1;
    const int warp_n = wid & 1;
    const int m_base = warp_m * 64;
    const int nb     = warp_n * 64;
    const int g = lane >> 2;
    const int t = lane & 3;
    const int lrow8 = (lane & 7) + ((lane >> 3) & 1) * 8;
    const int lk8   = ((lane >> 4) & 1) * 8;

    float acc[4][8][4];
#pragma unroll
    for (int i = 0; i < 4; i++)
#pragma unroll
        for (int j = 0; j < 8; j++)
#pragma unroll
            for (int r = 0; r < 4; r++) acc[i][j][r] = 0.0f;

    // ---- prologue: fill stage 0 ----
    ldg_A(0); sts_A(0);
    ldg_B(0); sts_B(0);
    __syncthreads();

#pragma unroll 1
    for (int kt = 0; kt < KT; kt++) {
        const int cur = kt & 1;
        const uint32_t AHb = sb + cur * SH_B;
        const uint32_t BHb = AHb + AH_B;

        // prefetch A for next stage
        if (kt + 1 < KT) ldg_A(kt + 1);

        // ---- k16 step 0 ----
        {
            const int k0 = 0;
            uint32_t af[4][4];
#pragma unroll
            for (int i = 0; i < 4; i++) {
                uint32_t addr = AHb
                    + (m_base + i * 16 + lrow8) * (A_STRIDE_H * 2)
                    + (k0 + lk8) * 2;
                ldmatrix_x4(af[i][0], af[i][1], af[i][2], af[i][3], addr);
            }
            uint32_t bf[4][4];
#pragma unroll
            for (int j2 = 0; j2 < 4; j2++) {
                uint32_t addr = BHb
                    + (k0 + lrow8) * (B_STRIDE_H * 2)
                    + (nb + j2 * 16 + lk8) * 2;
                ldmatrix_x4_trans(bf[j2][0], bf[j2][1], bf[j2][2], bf[j2][3], addr);
            }
#pragma unroll
            for (int i = 0; i < 4; i++)
#pragma unroll
                for (int j = 0; j < 8; j++) {
                    const int j2 = j >> 1, h = (j & 1) * 2;
                    mma_f16(acc[i][j][0], acc[i][j][1], acc[i][j][2], acc[i][j][3],
                            af[i][0], af[i][1], af[i][2], af[i][3],
                            bf[j2][h + 0], bf[j2][h + 1]);
                }
        }

        // store A(kt+1), then reuse pR to prefetch B(kt+1)
        if (kt + 1 < KT) {
            sts_A(cur ^ 1);
            ldg_B(kt + 1);
        }

        // ---- k16 step 1 ----
        {
            const int k0 = 16;
            uint32_t af[4][4];
#pragma unroll
            for (int i = 0; i < 4; i++) {
                uint32_t addr = AHb
                    + (m_base + i * 16 + lrow8) * (A_STRIDE_H * 2)
                    + (k0 + lk8) * 2;
                ldmatrix_x4(af[i][0], af[i][1], af[i][2], af[i][3], addr);
            }
            uint32_t bf[4][4];
#pragma unroll
            for (int j2 = 0; j2 < 4; j2++) {
                uint32_t addr = BHb
                    + (k0 + lrow8) * (B_STRIDE_H * 2)
                    + (nb + j2 * 16 + lk8) * 2;
                ldmatrix_x4_trans(bf[j2][0], bf[j2][1], bf[j2][2], bf[j2][3], addr);
            }
#pragma unroll
            for (int i = 0; i < 4; i++)
#pragma unroll
                for (int j = 0; j < 8; j++) {
                    const int j2 = j >> 1, h = (j & 1) * 2;
                    mma_f16(acc[i][j][0], acc[i][j][1], acc[i][j][2], acc[i][j][3],
                            af[i][0], af[i][1], af[i][2], af[i][3],
                            bf[j2][h + 0], bf[j2][h + 1]);
                }
        }

        // store B(kt+1); stage cur^1 now complete
        if (kt + 1 < KT) sts_B(cur ^ 1);
        __syncthreads();
    }

    // ---- epilogue (standard m16n8 C layout) ----
#pragma unroll
    for (int i = 0; i < 4; i++) {
        const int row0 = m_base + i * 16 + g;
#pragma unroll
        for (int j = 0; j < 8; j++) {
            const int col = nb + j * 8 + 2 * t;
            *(float2*)(Cb + (size_t)row0 * Nn + col) =
                make_float2(acc[i][j][0], acc[i][j][1]);
            *(float2*)(Cb + (size_t)(row0 + 8) * Nn + col) =
                make_float2(acc[i][j][2], acc[i][j][3]);
        }
    }
}

extern "C" void kernel_launch(void* const* d_in, const int* in_sizes, int n_in,
                              void* d_out, int out_size) {
    const float* x    = (const float*)d_in[0];  // [16, 256, 512]
    const float* path = (const float*)d_in[1];  // [16, 512, 2048]
    float* out = (float*)d_out;                 // [16, 256, 2048]

    dim3 grid(Nn / BN, Mm / BM, 16);  // (16, 2, 16) = 512 CTAs
    bmm_mma_f16_sp<<<grid, THREADS>>>(x, path, out);
}

// round 14
// speedup vs baseline: 1.6280x; 1.0762x over previous
#include <cuda_runtime.h>
#include <cstdint>

// Batched GEMM, mma.sync fp16 m16n8k16 + ldmatrix (round-9 core).
// Round-14: single change vs round 9 — the per-kt __syncthreads is hoisted
// ABOVE the ks=1 MMA block (right after the last smem reads/writes of the
// iteration). Each warp then carries 32 register-only MMAs past the barrier,
// overlapping the next iteration's LDSM/staging instead of serializing it.
//
//   x:    [B=16, M=256, K=512]  (K contiguous)
//   path: [B=16, K=512, N=2048] (N contiguous)
//   out:  [B=16, M=256, N=2048]
//
// CTA 128x128, BK=32, 128 threads (4 warps, 64x64 warp tiles), 2 CTAs/SM.

constexpr int Mm = 256, Kk = 512, Nn = 2048;
constexpr int BM = 128, BN = 128, BK = 32;
constexpr int THREADS = 128;
constexpr int KT = Kk / BK;  // 16

constexpr int A_STRIDE_H = 40;   // fp16 units (80B rows)
constexpr int B_STRIDE_H = 136;  // fp16 units (272B rows)
constexpr int AH_B = BM * A_STRIDE_H * 2;   // 10240 B
constexpr int BH_B = BK * B_STRIDE_H * 2;   // 8704 B
constexpr int SH_B = AH_B + BH_B;           // 18944 B

__device__ __forceinline__ uint32_t smem_u32(const void* ptr) {
    uint32_t a;
    asm("{ .reg .u64 t; cvta.to.shared.u64 t, %1; cvt.u32.u64 %0, t; }"
        : "=r"(a) : "l"(ptr));
    return a;
}
__device__ __forceinline__ uint32_t h2pack(float lo, float hi) {
    uint32_t r;
    asm("cvt.rn.f16x2.f32 %0, %1, %2;" : "=r"(r) : "f"(hi), "f"(lo));
    return r;
}
__device__ __forceinline__ void ldmatrix_x4(uint32_t& r0, uint32_t& r1,
                                            uint32_t& r2, uint32_t& r3, uint32_t addr) {
    asm volatile("ldmatrix.sync.aligned.m8n8.x4.shared.b16 {%0,%1,%2,%3}, [%4];"
                 : "=r"(r0), "=r"(r1), "=r"(r2), "=r"(r3) : "r"(addr));
}
__device__ __forceinline__ void ldmatrix_x4_trans(uint32_t& r0, uint32_t& r1,
                                                  uint32_t& r2, uint32_t& r3, uint32_t addr) {
    asm volatile("ldmatrix.sync.aligned.m8n8.x4.trans.shared.b16 {%0,%1,%2,%3}, [%4];"
                 : "=r"(r0), "=r"(r1), "=r"(r2), "=r"(r3) : "r"(addr));
}
__device__ __forceinline__ void mma_f16(float& c0, float& c1, float& c2, float& c3,
                                        uint32_t a0, uint32_t a1, uint32_t a2, uint32_t a3,
                                        uint32_t b0, uint32_t b1) {
    asm volatile(
        "mma.sync.aligned.m16n8k16.row.col.f32.f16.f16.f32 "
        "{%0,%1,%2,%3}, {%4,%5,%6,%7}, {%8,%9}, {%0,%1,%2,%3};"
        : "+f"(c0), "+f"(c1), "+f"(c2), "+f"(c3)
        : "r"(a0), "r"(a1), "r"(a2), "r"(a3), "r"(b0), "r"(b1));
}

__global__ __launch_bounds__(THREADS, 2)
void bmm_mma_f16_hb(const float* __restrict__ A,
                    const float* __restrict__ B,
                    float* __restrict__ C) {
    __shared__ __align__(16) char smem_raw[2 * SH_B];
    const uint32_t sb = smem_u32(smem_raw);

    const int tid = threadIdx.x;
    const int wid = tid >> 5;
    const int lane = tid & 31;
    const int b  = blockIdx.z;
    const int by = blockIdx.y;
    const int n0 = blockIdx.x * BN;

    const float* Ab = A + (size_t)b * Mm * Kk + (size_t)by * BM * Kk;
    const float* Bb = B + (size_t)b * Kk * Nn + n0;
    float*       Cb = C + (size_t)b * Mm * Nn + (size_t)by * BM * Nn + n0;

    // ---- staging mappings: 8 float4 chunks each of A and B per thread ----
    const float* aSrc[8];
    const float* bSrc[8];
    uint32_t aSt[8], bSt[8];
#pragma unroll
    for (int j = 0; j < 8; j++) {
        int i = j * 128 + tid;
        int row = i >> 3, kq = (i & 7) * 4;
        aSrc[j] = Ab + (size_t)row * Kk + kq;
        aSt[j] = row * (A_STRIDE_H * 2) + kq * 2;
        int krow = i >> 5, n = (i & 31) * 4;
        bSrc[j] = Bb + (size_t)krow * Nn + n;
        bSt[j] = AH_B + krow * (B_STRIDE_H * 2) + n * 2;
    }

    float4 aR[8], bR[8];

    auto ldg_stage = [&](int kt) {
#pragma unroll
        for (int j = 0; j < 8; j++) aR[j] = *(const float4*)(aSrc[j] + (size_t)kt * BK);
#pragma unroll
        for (int j = 0; j < 8; j++) bR[j] = *(const float4*)(bSrc[j] + (size_t)kt * BK * Nn);
    };
    auto sts_stage = [&](int s) {
        const uint32_t soff = s * SH_B;
#pragma unroll
        for (int j = 0; j < 8; j++) {
            uint2 p = make_uint2(h2pack(aR[j].x, aR[j].y), h2pack(aR[j].z, aR[j].w));
            *(uint2*)(smem_raw + aSt[j] + soff) = p;
        }
#pragma unroll
        for (int j = 0; j < 8; j++) {
            uint2 p = make_uint2(h2pack(bR[j].x, bR[j].y), h2pack(bR[j].z, bR[j].w));
            *(uint2*)(smem_raw + bSt[j] + soff) = p;
        }
    };

    // ---- compute mapping: 4 warps, 2x2 of 64x64 warp tiles ----
    const int warp_m = wid >> 1;
    const int warp_n = wid & 1;
    const int m_base = warp_m * 64;
    const int nb     = warp_n * 64;
    const int g = lane >> 2;
    const int t = lane & 3;
    const int lrow8 = (lane & 7) + ((lane >> 3) & 1) * 8;
    const int lk8   = ((lane >> 4) & 1) * 8;

    float acc[4][8][4];
#pragma unroll
    for (int i = 0; i < 4; i++)
#pragma unroll
        for (int j = 0; j < 8; j++)
#pragma unroll
            for (int r = 0; r < 4; r++) acc[i][j][r] = 0.0f;

    uint32_t af[4][4], bf[4][4];

    auto ldsm_frags = [&](uint32_t AHb, uint32_t BHb, int k0) {
#pragma unroll
        for (int i = 0; i < 4; i++) {
            uint32_t addr = AHb
                + (m_base + i * 16 + lrow8) * (A_STRIDE_H * 2)
                + (k0 + lk8) * 2;
            ldmatrix_x4(af[i][0], af[i][1], af[i][2], af[i][3], addr);
        }
#pragma unroll
        for (int j2 = 0; j2 < 4; j2++) {
            uint32_t addr = BHb
                + (k0 + lrow8) * (B_STRIDE_H * 2)
                + (nb + j2 * 16 + lk8) * 2;
            ldmatrix_x4_trans(bf[j2][0], bf[j2][1], bf[j2][2], bf[j2][3], addr);
        }
    };
    auto mma_block = [&]() {
#pragma unroll
        for (int i = 0; i < 4; i++)
#pragma unroll
            for (int j = 0; j < 8; j++) {
                const int j2 = j >> 1, h = (j & 1) * 2;
                mma_f16(acc[i][j][0], acc[i][j][1], acc[i][j][2], acc[i][j][3],
                        af[i][0], af[i][1], af[i][2], af[i][3],
                        bf[j2][h + 0], bf[j2][h + 1]);
            }
    };

    // prologue
    ldg_stage(0);
    sts_stage(0);
    __syncthreads();

#pragma unroll 1
    for (int kt = 0; kt < KT; kt++) {
        const int cur = kt & 1;
        const uint32_t AHb = sb + cur * SH_B;
        const uint32_t BHb = AHb + AH_B;

        if (kt + 1 < KT) ldg_stage(kt + 1);

        // ks = 0: LDSM + MMA
        ldsm_frags(AHb, BHb, 0);
        mma_block();

        // stage write for kt+1 (LDG latency covered by the ks0 MMA block)
        if (kt + 1 < KT) sts_stage(cur ^ 1);

        // ks = 1: LDSM (last smem reads of this stage)
        ldsm_frags(AHb, BHb, 16);

        // barrier hoisted here: all reads of `cur` and writes of `cur^1` done.
        __syncthreads();

        // ks = 1 MMAs are register-only — overlap the next iteration's head.
        mma_block();
    }

    // ---- epilogue (standard m16n8 C layout) ----
#pragma unroll
    for (int i = 0; i < 4; i++) {
        const int row0 = m_base + i * 16 + g;
#pragma unroll
        for (int j = 0; j < 8; j++) {
            const int col = nb + j * 8 + 2 * t;
            *(float2*)(Cb + (size_t)row0 * Nn + col) =
                make_float2(acc[i][j][0], acc[i][j][1]);
            *(float2*)(Cb + (size_t)(row0 + 8) * Nn + col) =
                make_float2(acc[i][j][2], acc[i][j][3]);
        }
    }
}

extern "C" void kernel_launch(void* const* d_in, const int* in_sizes, int n_in,
                              void* d_out, int out_size) {
    const float* x    = (const float*)d_in[0];  // [16, 256, 512]
    const float* path = (const float*)d_in[1];  // [16, 512, 2048]
    float* out = (float*)d_out;                 // [16, 256, 2048]

    dim3 grid(Nn / BN, Mm / BM, 16);  // (16, 2, 16) = 512 CTAs
    bmm_mma_f16_hb<<<grid, THREADS>>>(x, path, out);
}

// round 15
// speedup vs baseline: 1.8294x; 1.1237x over previous
#include <cuda_runtime.h>
#include <cstdint>

// Batched GEMM, mma.sync fp16 m16n8k16 + ldmatrix (round-9 warp-level core).
// Round-15: CTA tile widened to 128x256 (8 warps, 2x4 of the SAME 64x64 warp
// tile). A-tile global re-reads halve (16x -> 8x), cutting L1TEX bytes ~12%
// and L2/A traffic 2x. Warp-level code, strides, and staging math unchanged.
//
//   x:    [B=16, M=256, K=512]  (K contiguous)
//   path: [B=16, K=512, N=2048] (N contiguous)
//   out:  [B=16, M=256, N=2048]
//
// CTA 128x256, BK=32, 256 threads, 2-stage double buffer, 1 CTA/SM (8 warps).

constexpr int Mm = 256, Kk = 512, Nn = 2048;
constexpr int BM = 128, BN = 256, BK = 32;
constexpr int THREADS = 256;
constexpr int KT = Kk / BK;  // 16

constexpr int A_STRIDE_H = 40;   // fp16 units (80B rows) - proven
constexpr int B_STRIDE_H = 264;  // fp16 units (528B rows; same bank phase as 136)
constexpr int AH_B = BM * A_STRIDE_H * 2;   // 10240 B
constexpr int BH_B = BK * B_STRIDE_H * 2;   // 16896 B
constexpr int SH_B = AH_B + BH_B;           // 27136 B

__device__ __forceinline__ uint32_t smem_u32(const void* ptr) {
    uint32_t a;
    asm("{ .reg .u64 t; cvta.to.shared.u64 t, %1; cvt.u32.u64 %0, t; }"
        : "=r"(a) : "l"(ptr));
    return a;
}
__device__ __forceinline__ uint32_t h2pack(float lo, float hi) {
    uint32_t r;
    asm("cvt.rn.f16x2.f32 %0, %1, %2;" : "=r"(r) : "f"(hi), "f"(lo));
    return r;
}
__device__ __forceinline__ void ldmatrix_x4(uint32_t& r0, uint32_t& r1,
                                            uint32_t& r2, uint32_t& r3, uint32_t addr) {
    asm volatile("ldmatrix.sync.aligned.m8n8.x4.shared.b16 {%0,%1,%2,%3}, [%4];"
                 : "=r"(r0), "=r"(r1), "=r"(r2), "=r"(r3) : "r"(addr));
}
__device__ __forceinline__ void ldmatrix_x4_trans(uint32_t& r0, uint32_t& r1,
                                                  uint32_t& r2, uint32_t& r3, uint32_t addr) {
    asm volatile("ldmatrix.sync.aligned.m8n8.x4.trans.shared.b16 {%0,%1,%2,%3}, [%4];"
                 : "=r"(r0), "=r"(r1), "=r"(r2), "=r"(r3) : "r"(addr));
}
__device__ __forceinline__ void mma_f16(float& c0, float& c1, float& c2, float& c3,
                                        uint32_t a0, uint32_t a1, uint32_t a2, uint32_t a3,
                                        uint32_t b0, uint32_t b1) {
    asm volatile(
        "mma.sync.aligned.m16n8k16.row.col.f32.f16.f16.f32 "
        "{%0,%1,%2,%3}, {%4,%5,%6,%7}, {%8,%9}, {%0,%1,%2,%3};"
        : "+f"(c0), "+f"(c1), "+f"(c2), "+f"(c3)
        : "r"(a0), "r"(a1), "r"(a2), "r"(a3), "r"(b0), "r"(b1));
}

__global__ __launch_bounds__(THREADS, 1)
void bmm_mma_f16_w256(const float* __restrict__ A,
                      const float* __restrict__ B,
                      float* __restrict__ C) {
    __shared__ __align__(16) char smem_raw[2 * SH_B];
    const uint32_t sb = smem_u32(smem_raw);

    const int tid = threadIdx.x;
    const int wid = tid >> 5;
    const int lane = tid & 31;
    const int b  = blockIdx.z;
    const int by = blockIdx.y;
    const int n0 = blockIdx.x * BN;

    const float* Ab = A + (size_t)b * Mm * Kk + (size_t)by * BM * Kk;
    const float* Bb = B + (size_t)b * Kk * Nn + n0;
    float*       Cb = C + (size_t)b * Mm * Nn + (size_t)by * BM * Nn + n0;

    // ---- staging mappings ----
    // A tile: 128 rows x 32 floats = 1024 f4 chunks; 4/thread.
    //   chunk i = j*256+tid: row = i>>3, kq = (i&7)*4
    // B tile: 32 rows x 256 floats = 2048 f4 chunks; 8/thread.
    //   chunk i = j*256+tid: krow = i>>6, n = (i&63)*4
    const float* aSrc[4];
    const float* bSrc[8];
    uint32_t aSt[4], bSt[8];
#pragma unroll
    for (int j = 0; j < 4; j++) {
        int i = j * 256 + tid;
        int row = i >> 3, kq = (i & 7) * 4;
        aSrc[j] = Ab + (size_t)row * Kk + kq;
        aSt[j] = row * (A_STRIDE_H * 2) + kq * 2;
    }
#pragma unroll
    for (int j = 0; j < 8; j++) {
        int i = j * 256 + tid;
        int krow = i >> 6, n = (i & 63) * 4;
        bSrc[j] = Bb + (size_t)krow * Nn + n;
        bSt[j] = AH_B + krow * (B_STRIDE_H * 2) + n * 2;
    }

    float4 aR[4], bR[8];

    auto ldg_stage = [&](int kt) {
#pragma unroll
        for (int j = 0; j < 4; j++) aR[j] = *(const float4*)(aSrc[j] + (size_t)kt * BK);
#pragma unroll
        for (int j = 0; j < 8; j++) bR[j] = *(const float4*)(bSrc[j] + (size_t)kt * BK * Nn);
    };
    auto sts_stage = [&](int s) {
        const uint32_t soff = s * SH_B;
#pragma unroll
        for (int j = 0; j < 4; j++) {
            uint2 p = make_uint2(h2pack(aR[j].x, aR[j].y), h2pack(aR[j].z, aR[j].w));
            *(uint2*)(smem_raw + aSt[j] + soff) = p;
        }
#pragma unroll
        for (int j = 0; j < 8; j++) {
            uint2 p = make_uint2(h2pack(bR[j].x, bR[j].y), h2pack(bR[j].z, bR[j].w));
            *(uint2*)(smem_raw + bSt[j] + soff) = p;
        }
    };

    // ---- compute mapping: 8 warps, 2x4 of 64x64 warp tiles ----
    const int warp_m = wid >> 2;        // 0..1
    const int warp_n = wid & 3;         // 0..3
    const int m_base = warp_m * 64;
    const int nb     = warp_n * 64;
    const int g = lane >> 2;
    const int t = lane & 3;
    const int lrow8 = (lane & 7) + ((lane >> 3) & 1) * 8;
    const int lk8   = ((lane >> 4) & 1) * 8;

    float acc[4][8][4];
#pragma unroll
    for (int i = 0; i < 4; i++)
#pragma unroll
        for (int j = 0; j < 8; j++)
#pragma unroll
            for (int r = 0; r < 4; r++) acc[i][j][r] = 0.0f;

    // prologue
    ldg_stage(0);
    sts_stage(0);
    __syncthreads();

#pragma unroll 1
    for (int kt = 0; kt < KT; kt++) {
        const int cur = kt & 1;

        if (kt + 1 < KT) ldg_stage(kt + 1);

        const uint32_t AHb = sb + cur * SH_B;
        const uint32_t BHb = AHb + AH_B;

#pragma unroll
        for (int ks = 0; ks < 2; ks++) {     // 2 x k16 per BK=32
            const int k0 = ks * 16;

            uint32_t af[4][4];
#pragma unroll
            for (int i = 0; i < 4; i++) {
                uint32_t addr = AHb
                    + (m_base + i * 16 + lrow8) * (A_STRIDE_H * 2)
                    + (k0 + lk8) * 2;
                ldmatrix_x4(af[i][0], af[i][1], af[i][2], af[i][3], addr);
            }
            uint32_t bf[4][4];
#pragma unroll
            for (int j2 = 0; j2 < 4; j2++) {
                uint32_t addr = BHb
                    + (k0 + lrow8) * (B_STRIDE_H * 2)
                    + (nb + j2 * 16 + lk8) * 2;
                ldmatrix_x4_trans(bf[j2][0], bf[j2][1], bf[j2][2], bf[j2][3], addr);
            }
#pragma unroll
            for (int i = 0; i < 4; i++)
#pragma unroll
                for (int j = 0; j < 8; j++) {
                    const int j2 = j >> 1, h = (j & 1) * 2;
                    mma_f16(acc[i][j][0], acc[i][j][1], acc[i][j][2], acc[i][j][3],
                            af[i][0], af[i][1], af[i][2], af[i][3],
                            bf[j2][h + 0], bf[j2][h + 1]);
                }
        }

        if (kt + 1 < KT) sts_stage(cur ^ 1);
        __syncthreads();
    }

    // ---- epilogue (standard m16n8 C layout) ----
#pragma unroll
    for (int i = 0; i < 4; i++) {
        const int row0 = m_base + i * 16 + g;
#pragma unroll
        for (int j = 0; j < 8; j++) {
            const int col = nb + j * 8 + 2 * t;
            *(float2*)(Cb + (size_t)row0 * Nn + col) =
                make_float2(acc[i][j][0], acc[i][j][1]);
            *(float2*)(Cb + (size_t)(row0 + 8) * Nn + col) =
                make_float2(acc[i][j][2], acc[i][j][3]);
        }
    }
}

extern "C" void kernel_launch(void* const* d_in, const int* in_sizes, int n_in,
                              void* d_out, int out_size) {
    const float* x    = (const float*)d_in[0];  // [16, 256, 512]
    const float* path = (const float*)d_in[1];  // [16, 512, 2048]
    float* out = (float*)d_out;                 // [16, 256, 2048]

    dim3 grid(Nn / BN, Mm / BM, 16);  // (8, 2, 16) = 256 CTAs
    bmm_mma_f16_w256<<<grid, THREADS>>>(x, path, out);
}

// round 16
// speedup vs baseline: 1.9193x; 1.0491x over previous
#include <cuda_runtime.h>
#include <cstdint>

// Batched GEMM, mma.sync fp16 m16n8k16 + ldmatrix — session-best kernel (R9),
// re-validated as final. 234.4us (fp32 SIMT baseline) -> 47.1us here (5.0x).
//
// Design (each element evidence-driven across 15 benched rounds):
//  - fp16 HMMA (2x MAC rate of tf32, which R5/R6 measured as saturated);
//    inputs rounded once to fp16 during staging (rel_err 2.8e-4 < 1e-3).
//  - smem holds fp16 tiles; operands fed by ldmatrix.x4 (16 ops + 64 HMMA
//    per warp-kt; the LDS/cvt-per-fragment variants measured 20-60% slower).
//  - CTA 128x128, BK=32, 128 threads, 4 warps of 64x64 (the measured-optimal
//    warp shape: 64x32 added 50% LDSM redundancy and regressed).
//  - 2-stage smem double buffer + whole-stage register prefetch; every
//    alternative staging scheme (cp.async+convert pass, producer warp,
//    split prefetch, hoisted barrier, 128x256 tiles) benched worse or equal.
//  - 255-reg/thread ISA cap is the binding constraint (acc 128 + frags 32 +
//    prefetch 64 + addressing ~= 254); L1TEX and tensor pipes co-bind at
//    ~1.1:1.0 k-cycles per SM-kt => ~43.8us ncu compute is the plateau for
//    the mma.sync path on this harness (tcgen05 is blocked: plain sm_103).
//
//   x:    [B=16, M=256, K=512]  (K contiguous)
//   path: [B=16, K=512, N=2048] (N contiguous)
//   out:  [B=16, M=256, T=2048]

constexpr int Mm = 256, Kk = 512, Nn = 2048;
constexpr int BM = 128, BN = 128, BK = 32;
constexpr int THREADS = 128;
constexpr int KT = Kk / BK;  // 16

constexpr int A_STRIDE_H = 40;   // fp16 units (80B rows: conflict-free STS + LDSM)
constexpr int B_STRIDE_H = 136;  // fp16 units (272B rows: conflict-free STS + trans-LDSM)
constexpr int AH_B = BM * A_STRIDE_H * 2;   // 10240 B
constexpr int BH_B = BK * B_STRIDE_H * 2;   // 8704 B
constexpr int SH_B = AH_B + BH_B;           // 18944 B

__device__ __forceinline__ uint32_t smem_u32(const void* ptr) {
    uint32_t a;
    asm("{ .reg .u64 t; cvta.to.shared.u64 t, %1; cvt.u32.u64 %0, t; }"
        : "=r"(a) : "l"(ptr));
    return a;
}

// pack two fp32 into f16x2: lo half = first arg, hi half = second arg
__device__ __forceinline__ uint32_t h2pack(float lo, float hi) {
    uint32_t r;
    asm("cvt.rn.f16x2.f32 %0, %1, %2;" : "=r"(r) : "f"(hi), "f"(lo));
    return r;
}

__device__ __forceinline__ void ldmatrix_x4(uint32_t& r0, uint32_t& r1,
                                            uint32_t& r2, uint32_t& r3, uint32_t addr) {
    asm volatile("ldmatrix.sync.aligned.m8n8.x4.shared.b16 {%0,%1,%2,%3}, [%4];"
                 : "=r"(r0), "=r"(r1), "=r"(r2), "=r"(r3) : "r"(addr));
}
__device__ __forceinline__ void ldmatrix_x4_trans(uint32_t& r0, uint32_t& r1,
                                                  uint32_t& r2, uint32_t& r3, uint32_t addr) {
    asm volatile("ldmatrix.sync.aligned.m8n8.x4.trans.shared.b16 {%0,%1,%2,%3}, [%4];"
                 : "=r"(r0), "=r"(r1), "=r"(r2), "=r"(r3) : "r"(addr));
}

__device__ __forceinline__ void mma_f16(float& c0, float& c1, float& c2, float& c3,
                                        uint32_t a0, uint32_t a1, uint32_t a2, uint32_t a3,
                                        uint32_t b0, uint32_t b1) {
    asm volatile(
        "mma.sync.aligned.m16n8k16.row.col.f32.f16.f16.f32 "
        "{%0,%1,%2,%3}, {%4,%5,%6,%7}, {%8,%9}, {%0,%1,%2,%3};"
        : "+f"(c0), "+f"(c1), "+f"(c2), "+f"(c3)
        : "r"(a0), "r"(a1), "r"(a2), "r"(a3), "r"(b0), "r"(b1));
}

__global__ __launch_bounds__(THREADS, 2)
void bmm_mma_f16_ldm(const float* __restrict__ A,
                     const float* __restrict__ B,
                     float* __restrict__ C) {
    __shared__ __align__(16) char smem_raw[2 * SH_B];
    const uint32_t sb = smem_u32(smem_raw);

    const int tid = threadIdx.x;
    const int wid = tid >> 5;
    const int lane = tid & 31;
    const int b  = blockIdx.z;
    const int by = blockIdx.y;
    const int n0 = blockIdx.x * BN;

    const float* Ab = A + (size_t)b * Mm * Kk + (size_t)by * BM * Kk;
    const float* Bb = B + (size_t)b * Kk * Nn + n0;
    float*       Cb = C + (size_t)b * Mm * Nn + (size_t)by * BM * Nn + n0;

    // ---- staging mappings: 8 float4 chunks each of A and B per thread ----
    // A tile: 128 rows x 32 floats -> chunk i: row = i>>3, kq = (i&7)*4
    // B tile: 32 rows x 128 floats -> chunk i: krow = i>>5, n = (i&31)*4
    const float* aSrc[8];
    const float* bSrc[8];
    uint32_t aSt[8], bSt[8];
#pragma unroll
    for (int j = 0; j < 8; j++) {
        int i = j * 128 + tid;
        int row = i >> 3, kq = (i & 7) * 4;
        aSrc[j] = Ab + (size_t)row * Kk + kq;
        aSt[j] = sb + row * (A_STRIDE_H * 2) + kq * 2;
        int krow = i >> 5, n = (i & 31) * 4;
        bSrc[j] = Bb + (size_t)krow * Nn + n;
        bSt[j] = sb + AH_B + krow * (B_STRIDE_H * 2) + n * 2;
    }

    float4 aR[8], bR[8];

    auto ldg_stage = [&](int kt) {
#pragma unroll
        for (int j = 0; j < 8; j++) aR[j] = *(const float4*)(aSrc[j] + (size_t)kt * BK);
#pragma unroll
        for (int j = 0; j < 8; j++) bR[j] = *(const float4*)(bSrc[j] + (size_t)kt * BK * Nn);
    };
    auto sts_stage = [&](int s) {
        const uint32_t soff = s * SH_B;
#pragma unroll
        for (int j = 0; j < 8; j++) {
            uint2 p = make_uint2(h2pack(aR[j].x, aR[j].y), h2pack(aR[j].z, aR[j].w));
            *(uint2*)(smem_raw + (aSt[j] - sb) + soff) = p;
        }
#pragma unroll
        for (int j = 0; j < 8; j++) {
            uint2 p = make_uint2(h2pack(bR[j].x, bR[j].y), h2pack(bR[j].z, bR[j].w));
            *(uint2*)(smem_raw + (bSt[j] - sb) + soff) = p;
        }
    };

    // ---- compute mapping: 4 warps, 2x2 of 64x64 warp tiles ----
    const int warp_m = wid >> 1;
    const int warp_n = wid & 1;
    const int m_base = warp_m * 64;
    const int nb     = warp_n * 64;
    const int g = lane >> 2;
    const int t = lane & 3;

    // ldmatrix lane-address components
    const int lrow8 = (lane & 7) + ((lane >> 3) & 1) * 8;  // row within 16
    const int lk8   = ((lane >> 4) & 1) * 8;               // k/n half select

    float acc[4][8][4];
#pragma unroll
    for (int i = 0; i < 4; i++)
#pragma unroll
        for (int j = 0; j < 8; j++)
#pragma unroll
            for (int r = 0; r < 4; r++) acc[i][j][r] = 0.0f;

    // prologue
    ldg_stage(0);
    sts_stage(0);
    __syncthreads();

#pragma unroll 1
    for (int kt = 0; kt < KT; kt++) {
        const int cur = kt & 1;

        if (kt + 1 < KT) ldg_stage(kt + 1);

        const uint32_t Abase = sb + cur * SH_B;
        const uint32_t Bbase = Abase + AH_B;

#pragma unroll
        for (int ks = 0; ks < 2; ks++) {     // 2 x k16 per BK=32
            const int k0 = ks * 16;

            uint32_t af[4][4];
#pragma unroll
            for (int i = 0; i < 4; i++) {
                uint32_t addr = Abase
                    + (m_base + i * 16 + lrow8) * (A_STRIDE_H * 2)
                    + (k0 + lk8) * 2;
                ldmatrix_x4(af[i][0], af[i][1], af[i][2], af[i][3], addr);
            }
            uint32_t bf[4][4];  // [n16 tile][r0=b0 lo, r1=b1 lo, r2=b0 hi, r3=b1 hi]
#pragma unroll
            for (int j2 = 0; j2 < 4; j2++) {
                uint32_t addr = Bbase
                    + (k0 + lrow8) * (B_STRIDE_H * 2)
                    + (nb + j2 * 16 + lk8) * 2;
                ldmatrix_x4_trans(bf[j2][0], bf[j2][1], bf[j2][2], bf[j2][3], addr);
            }
#pragma unroll
            for (int i = 0; i < 4; i++)
#pragma unroll
                for (int j = 0; j < 8; j++) {
                    const int j2 = j >> 1, h = (j & 1) * 2;
                    mma_f16(acc[i][j][0], acc[i][j][1], acc[i][j][2], acc[i][j][3],
                            af[i][0], af[i][1], af[i][2], af[i][3],
                            bf[j2][h + 0], bf[j2][h + 1]);
                }
        }

        if (kt + 1 < KT) sts_stage(cur ^ 1);
        __syncthreads();
    }

    // ---- epilogue (standard m16n8 C layout) ----
#pragma unroll
    for (int i = 0; i < 4; i++) {
        const int row0 = m_base + i * 16 + g;
#pragma unroll
        for (int j = 0; j < 8; j++) {
            const int col = nb + j * 8 + 2 * t;
            *(float2*)(Cb + (size_t)row0 * Nn + col) =
                make_float2(acc[i][j][0], acc[i][j][1]);
            *(float2*)(Cb + (size_t)(row0 + 8) * Nn + col) =
                make_float2(acc[i][j][2], acc[i][j][3]);
        }
    }
}

extern "C" void kernel_launch(void* const* d_in, const int* in_sizes, int n_in,
                              void* d_out, int out_size) {
    const float* x    = (const float*)d_in[0];  // [16, 256, 512]
    const float* path = (const float*)d_in[1];  // [16, 512, 2048]
    float* out = (float*)d_out;                 // [16, 256, 2048]

    dim3 grid(Nn / BN, Mm / BM, 16);  // (16, 2, 16) = 512 CTAs
    bmm_mma_f16_ldm<<<grid, THREADS>>>(x, path, out);
}

// round 17
// speedup vs baseline: 1.9949x; 1.0394x over previous
#include <cuda_runtime.h>
#include <cstdint>

// Batched GEMM, mma.sync fp16 m16n8k16 + ldmatrix (round-9 core).
// Round-17: strength-reduced addressing. All 16 staging LDGs become
// immediate-offset loads from TWO 64-bit bases (chunk stride is a constant
// 8192 floats for both A and B); all 16 STS use two 32-bit base offsets with
// constant immediates (1280B / 1088B chunk strides); the 16 per-kt ldmatrix
// addresses reduce to 8 precomputed lane offsets + stage base + immediate.
// Frees ~40 registers at the 254-reg wall and ~40 ALU ops/kt/thread.
//
//   x:    [B=16, M=256, K=512]  (K contiguous)
//   path: [B=16, K=512, N=2048] (N contiguous)
//   out:  [B=16, M=256, N=2048]
//
// CTA 128x128, BK=32, 128 threads (4 warps, 64x64 warp tiles), 2 CTAs/SM.

constexpr int Mm = 256, Kk = 512, Nn = 2048;
constexpr int BM = 128, BN = 128, BK = 32;
constexpr int THREADS = 128;
constexpr int KT = Kk / BK;  // 16

constexpr int A_STRIDE_H = 40;   // fp16 units (80B rows)
constexpr int B_STRIDE_H = 136;  // fp16 units (272B rows)
constexpr int AH_B = BM * A_STRIDE_H * 2;   // 10240 B
constexpr int BH_B = BK * B_STRIDE_H * 2;   // 8704 B
constexpr int SH_B = AH_B + BH_B;           // 18944 B

__device__ __forceinline__ uint32_t smem_u32(const void* ptr) {
    uint32_t a;
    asm("{ .reg .u64 t; cvta.to.shared.u64 t, %1; cvt.u32.u64 %0, t; }"
        : "=r"(a) : "l"(ptr));
    return a;
}
__device__ __forceinline__ uint32_t h2pack(float lo, float hi) {
    uint32_t r;
    asm("cvt.rn.f16x2.f32 %0, %1, %2;" : "=r"(r) : "f"(hi), "f"(lo));
    return r;
}
__device__ __forceinline__ void ldmatrix_x4(uint32_t& r0, uint32_t& r1,
                                            uint32_t& r2, uint32_t& r3, uint32_t addr) {
    asm volatile("ldmatrix.sync.aligned.m8n8.x4.shared.b16 {%0,%1,%2,%3}, [%4];"
                 : "=r"(r0), "=r"(r1), "=r"(r2), "=r"(r3) : "r"(addr));
}
__device__ __forceinline__ void ldmatrix_x4_trans(uint32_t& r0, uint32_t& r1,
                                                  uint32_t& r2, uint32_t& r3, uint32_t addr) {
    asm volatile("ldmatrix.sync.aligned.m8n8.x4.trans.shared.b16 {%0,%1,%2,%3}, [%4];"
                 : "=r"(r0), "=r"(r1), "=r"(r2), "=r"(r3) : "r"(addr));
}
__device__ __forceinline__ void mma_f16(float& c0, float& c1, float& c2, float& c3,
                                        uint32_t a0, uint32_t a1, uint32_t a2, uint32_t a3,
                                        uint32_t b0, uint32_t b1) {
    asm volatile(
        "mma.sync.aligned.m16n8k16.row.col.f32.f16.f16.f32 "
        "{%0,%1,%2,%3}, {%4,%5,%6,%7}, {%8,%9}, {%0,%1,%2,%3};"
        : "+f"(c0), "+f"(c1), "+f"(c2), "+f"(c3)
        : "r"(a0), "r"(a1), "r"(a2), "r"(a3), "r"(b0), "r"(b1));
}

__global__ __launch_bounds__(THREADS, 2)
void bmm_mma_f16_sr(const float* __restrict__ A,
                    const float* __restrict__ B,
                    float* __restrict__ C) {
    __shared__ __align__(16) char smem_raw[2 * SH_B];
    const uint32_t sb = smem_u32(smem_raw);

    const int tid = threadIdx.x;
    const int wid = tid >> 5;
    const int lane = tid & 31;
    const int b  = blockIdx.z;
    const int by = blockIdx.y;
    const int n0 = blockIdx.x * BN;

    const float* Ab = A + (size_t)b * Mm * Kk + (size_t)by * BM * Kk;
    const float* Bb = B + (size_t)b * Kk * Nn + n0;
    float*       Cb = C + (size_t)b * Mm * Nn + (size_t)by * BM * Nn + n0;

    // ---- strength-reduced staging bases ----
    // chunk i = j*128+tid. A: row = j*16 + (tid>>3), kq = (tid&7)*4
    //   -> global: aG + j*8192 floats (+kt*32); smem: aS0 + j*1280 bytes.
    // B: krow = j*4 + (tid>>5), n = (tid&31)*4
    //   -> global: bG + j*8192 floats (+kt*32*2048); smem: bS0 + j*1088 bytes.
    const float* aG = Ab + (size_t)(tid >> 3) * Kk + (tid & 7) * 4;
    const float* bG = Bb + (size_t)(tid >> 5) * Nn + (tid & 31) * 4;
    const uint32_t aS0 = (tid >> 3) * 80 + (tid & 7) * 8;           // bytes
    const uint32_t bS0 = AH_B + (tid >> 5) * 272 + (tid & 31) * 8;  // bytes

    float4 aR[8], bR[8];

    auto ldg_stage = [&](int kt) {
        const float* a = aG + kt * BK;
#pragma unroll
        for (int j = 0; j < 8; j++) aR[j] = *(const float4*)(a + j * 8192);
        const float* bp = bG + (size_t)kt * BK * Nn;
#pragma unroll
        for (int j = 0; j < 8; j++) bR[j] = *(const float4*)(bp + j * 8192);
    };
    auto sts_stage = [&](int s) {
        char* base = smem_raw + s * SH_B;
#pragma unroll
        for (int j = 0; j < 8; j++) {
            uint2 p = make_uint2(h2pack(aR[j].x, aR[j].y), h2pack(aR[j].z, aR[j].w));
            *(uint2*)(base + aS0 + j * 1280) = p;
        }
#pragma unroll
        for (int j = 0; j < 8; j++) {
            uint2 p = make_uint2(h2pack(bR[j].x, bR[j].y), h2pack(bR[j].z, bR[j].w));
            *(uint2*)(base + bS0 + j * 1088) = p;
        }
    };

    // ---- compute mapping: 4 warps, 2x2 of 64x64 warp tiles ----
    const int warp_m = wid >> 1;
    const int warp_n = wid & 1;
    const int m_base = warp_m * 64;
    const int nb     = warp_n * 64;
    const int g = lane >> 2;
    const int t = lane & 3;
    const int lrow8 = (lane & 7) + ((lane >> 3) & 1) * 8;
    const int lk8   = ((lane >> 4) & 1) * 8;

    // precomputed ldmatrix lane offsets (bytes within a stage)
    uint32_t aAd[4], bAd[4];
#pragma unroll
    for (int i = 0; i < 4; i++)
        aAd[i] = (m_base + i * 16 + lrow8) * 80 + lk8 * 2;
#pragma unroll
    for (int j2 = 0; j2 < 4; j2++)
        bAd[j2] = AH_B + lrow8 * 272 + (nb + j2 * 16 + lk8) * 2;

    float acc[4][8][4];
#pragma unroll
    for (int i = 0; i < 4; i++)
#pragma unroll
        for (int j = 0; j < 8; j++)
#pragma unroll
            for (int r = 0; r < 4; r++) acc[i][j][r] = 0.0f;

    // prologue
    ldg_stage(0);
    sts_stage(0);
    __syncthreads();

#pragma unroll 1
    for (int kt = 0; kt < KT; kt++) {
        const int cur = kt & 1;
        const uint32_t stb = sb + cur * SH_B;

        if (kt + 1 < KT) ldg_stage(kt + 1);

#pragma unroll
        for (int ks = 0; ks < 2; ks++) {     // 2 x k16 per BK=32
            const uint32_t kA = ks * 32;     // k0*2 bytes (A, K-contiguous)
            const uint32_t kB = ks * 4352;   // k0*272 bytes (B, 16 rows)

            uint32_t af[4][4];
#pragma unroll
            for (int i = 0; i < 4; i++)
                ldmatrix_x4(af[i][0], af[i][1], af[i][2], af[i][3],
                            stb + aAd[i] + kA);
            uint32_t bf[4][4];
#pragma unroll
            for (int j2 = 0; j2 < 4; j2++)
                ldmatrix_x4_trans(bf[j2][0], bf[j2][1], bf[j2][2], bf[j2][3],
                                  stb + bAd[j2] + kB);
#pragma unroll
            for (int i = 0; i < 4; i++)
#pragma unroll
                for (int j = 0; j < 8; j++) {
                    const int j2 = j >> 1, h = (j & 1) * 2;
                    mma_f16(acc[i][j][0], acc[i][j][1], acc[i][j][2], acc[i][j][3],
                            af[i][0], af[i][1], af[i][2], af[i][3],
                            bf[j2][h + 0], bf[j2][h + 1]);
                }
        }

        if (kt + 1 < KT) sts_stage(cur ^ 1);
        __syncthreads();
    }

    // ---- epilogue (standard m16n8 C layout) ----
#pragma unroll
    for (int i = 0; i < 4; i++) {
        const int row0 = m_base + i * 16 + g;
#pragma unroll
        for (int j = 0; j < 8; j++) {
            const int col = nb + j * 8 + 2 * t;
            *(float2*)(Cb + (size_t)row0 * Nn + col) =
                make_float2(acc[i][j][0], acc[i][j][1]);
            *(float2*)(Cb + (size_t)(row0 + 8) * Nn + col) =
                make_float2(acc[i][j][2], acc[i][j][3]);
        }
    }
}

extern "C" void kernel_launch(void* const* d_in, const int* in_sizes, int n_in,
                              void* d_out, int out_size) {
    const float* x    = (const float*)d_in[0];  // [16, 256, 512]
    const float* path = (const float*)d_in[1];  // [16, 512, 2048]
    float* out = (float*)d_out;                 // [16, 256, 2048]

    dim3 grid(Nn / BN, Mm / BM, 16);  // (16, 2, 16) = 512 CTAs
    bmm_mma_f16_sr<<<grid, THREADS>>>(x, path, out);
}